// round 16
// baseline (speedup 1.0000x reference)
#include <cuda_runtime.h>

// Problem constants (fixed by the reference)
#define G_   131072
#define NPG_ 38
#define NTOT (G_ * NPG_)        // 4,980,736 nodes
#define ETOT (10 * NTOT)        // 49,807,360 edges

// Per-node aggregate scratch (~19.9 MB static device array).
// Zeroed by a memset node each replay; edge atomics accumulate into it;
// head kernel adds the root term on read.
__device__ float g_nodes[NTOT];

// ---------------------------------------------------------------------------
// Edge kernel: per-edge message + scatter-add, 4 edges/thread, one-shot.
//   theta = edge_attr * w_edge + b_edge
//   g_nodes[dst] += x[src] * theta        (RED.ADD, spread addresses)
// At the joint HW floor: ~2.0 cyc/edge/SM of L1tex wavefront work + LTS
// sector traffic ~85% of cap; DRAM carries only the 600MB stream.
// Session evidence: ILP-insensitive (R1==R2); __ldcs helps (R3);
// persistence costs +80us (R12); TPB 256->512 saved ~2us (R15, fewer
// block-scheduling events).  THIS ROUND: TPB 512 -> 1024, same mechanism,
// same resident geometry (2048 thr/SM).
// ---------------------------------------------------------------------------
#define EVEC (ETOT / 4)         // 12,451,840 vec4 edge-groups
#define ETPB 1024

__global__ void __launch_bounds__(ETPB)
edge_kernel(const int*   __restrict__ edge_index,
            const float* __restrict__ edge_attr,
            const float* __restrict__ x,
            const float* __restrict__ w_edge,
            const float* __restrict__ b_edge) {
    int i = blockIdx.x * blockDim.x + threadIdx.x;   // over EVEC
    const int4*   src4 = reinterpret_cast<const int4*>(edge_index);
    const int4*   dst4 = reinterpret_cast<const int4*>(edge_index + ETOT);
    const float4* ea4  = reinterpret_cast<const float4*>(edge_attr);

    int4   s = __ldcs(&src4[i]);
    int4   d = __ldcs(&dst4[i]);
    float4 a = __ldcs(&ea4[i]);

    const float we = __ldg(w_edge);
    const float be = __ldg(b_edge);

    // independent gathers first (MLP), then the reductions
    float x0 = __ldg(x + s.x);
    float x1 = __ldg(x + s.y);
    float x2 = __ldg(x + s.z);
    float x3 = __ldg(x + s.w);

    atomicAdd(g_nodes + d.x, x0 * fmaf(a.x, we, be));
    atomicAdd(g_nodes + d.y, x1 * fmaf(a.y, we, be));
    atomicAdd(g_nodes + d.z, x2 * fmaf(a.z, we, be));
    atomicAdd(g_nodes + d.w, x3 * fmaf(a.w, we, be));
}

// ---------------------------------------------------------------------------
// Head kernel (CONVERGED, R11 best): nodes = g_nodes + x*w_root + b_conv,
// then per-graph MLP 38 -> 4 -> 4 -> 12 + softmax.
// 128 graphs/block (grid=1024), 1 thread per graph.  Staging loop fully
// unrolled (10 predicated iters) so ptxas batches the independent LDG.128s
// ahead of the shared stores; __launch_bounds__(128,7) gives the 72-reg
// budget for that batching without losing resident warps.  READ-ONLY
// staging (R7: stores into g_nodes cost +40us).
// ---------------------------------------------------------------------------
#define GPB   128
#define NVEC  ((GPB * NPG_) / 4)   // 1216 float4 per block

__global__ void __launch_bounds__(GPB, 7)
head_kernel(const float* __restrict__ x,
            const float* __restrict__ w_root, const float* __restrict__ b_conv,
            const float* __restrict__ W1, const float* __restrict__ b1,
            const float* __restrict__ W2, const float* __restrict__ b2,
            const float* __restrict__ W3, const float* __restrict__ b3,
            float* __restrict__ out) {
    __shared__ float sW1[NPG_ * 4];
    __shared__ float sb1[4];
    __shared__ float sW2[16];
    __shared__ float sb2[4];
    __shared__ float sW3[48];
    __shared__ float sb3[12];
    __shared__ float4 sn4[NVEC];               // linear GPB*38 floats

    const int t = threadIdx.x;

    // weight staging (block has 128 threads)
    if (t < 4)   sb1[t] = b1[t];
    if (t < 16)  sW2[t] = W2[t];
    if (t >= 16 && t < 20)  sb2[t - 16] = b2[t - 16];
    if (t >= 32 && t < 44)  sb3[t - 32] = b3[t - 32];
    if (t >= 48 && t < 96)  sW3[t - 48] = W3[t - 48];
    if (t < NPG_ * 4 - 128) sW1[128 + t] = W1[128 + t];  // elems 128..151
    sW1[t] = W1[t];                                      // elems 0..127

    const float wr = __ldg(w_root);
    const float bc = __ldg(b_conv);

    const long long base = (long long)blockIdx.x * (GPB * NPG_);
    const float4* agg4 = reinterpret_cast<const float4*>(g_nodes + base);
    const float4* x4   = reinterpret_cast<const float4*>(x + base);

    // staging: fold root term. Fully unrolled -> batched independent LDGs.
#pragma unroll
    for (int j = 0; j < 10; j++) {
        int k = t + j * GPB;
        if (k < NVEC) {
            float4 av = __ldcs(&agg4[k]);     // dead after this read
            float4 xv = __ldcs(&x4[k]);       // dead after this read
            float4 v;
            v.x = fmaf(xv.x, wr, bc) + av.x;
            v.y = fmaf(xv.y, wr, bc) + av.y;
            v.z = fmaf(xv.z, wr, bc) + av.z;
            v.w = fmaf(xv.w, wr, bc) + av.w;
            sn4[k] = v;
        }
    }
    __syncthreads();

    const float* h0 = reinterpret_cast<const float*>(sn4) + t * NPG_;

    // layer 1: 38 -> 4
    float h1[4];
#pragma unroll
    for (int j = 0; j < 4; j++) h1[j] = sb1[j];
#pragma unroll
    for (int k = 0; k < NPG_; k++) {
        float v = h0[k];
#pragma unroll
        for (int j = 0; j < 4; j++) h1[j] = fmaf(v, sW1[k * 4 + j], h1[j]);
    }
#pragma unroll
    for (int j = 0; j < 4; j++) h1[j] = (h1[j] >= 0.0f) ? h1[j] : 0.01f * h1[j];

    // layer 2: 4 -> 4
    float h2[4];
#pragma unroll
    for (int j = 0; j < 4; j++) h2[j] = sb2[j];
#pragma unroll
    for (int k = 0; k < 4; k++) {
        float v = h1[k];
#pragma unroll
        for (int j = 0; j < 4; j++) h2[j] = fmaf(v, sW2[k * 4 + j], h2[j]);
    }
#pragma unroll
    for (int j = 0; j < 4; j++) h2[j] = (h2[j] >= 0.0f) ? h2[j] : 0.01f * h2[j];

    // layer 3: 4 -> 12
    float h3[12];
#pragma unroll
    for (int j = 0; j < 12; j++) h3[j] = sb3[j];
#pragma unroll
    for (int k = 0; k < 4; k++) {
        float v = h2[k];
#pragma unroll
        for (int j = 0; j < 12; j++) h3[j] = fmaf(v, sW3[k * 12 + j], h3[j]);
    }
#pragma unroll
    for (int j = 0; j < 12; j++) h3[j] = (h3[j] >= 0.0f) ? h3[j] : 0.01f * h3[j];

    // stable softmax over 12
    float m = h3[0];
#pragma unroll
    for (int j = 1; j < 12; j++) m = fmaxf(m, h3[j]);
    float ssum = 0.0f;
#pragma unroll
    for (int j = 0; j < 12; j++) {
        h3[j] = __expf(h3[j] - m);
        ssum += h3[j];
    }
    float inv = 1.0f / ssum;

    // 12 floats = 3x STG.128, streaming (output is dead to this kernel)
    float4* o4 = reinterpret_cast<float4*>(out + ((long long)blockIdx.x * GPB + t) * 12);
    float4 o;
    o.x = h3[0] * inv;  o.y = h3[1] * inv;  o.z = h3[2] * inv;  o.w = h3[3] * inv;
    __stcs(&o4[0], o);
    o.x = h3[4] * inv;  o.y = h3[5] * inv;  o.z = h3[6] * inv;  o.w = h3[7] * inv;
    __stcs(&o4[1], o);
    o.x = h3[8] * inv;  o.y = h3[9] * inv;  o.z = h3[10] * inv; o.w = h3[11] * inv;
    __stcs(&o4[2], o);
}

// ---------------------------------------------------------------------------
// Launch.  Inputs: x, edge_index, edge_attr, w_edge, b_edge, w_root, b_conv,
//                  W1, b1, W2, b2, W3, b3
// ---------------------------------------------------------------------------
extern "C" void kernel_launch(void* const* d_in, const int* in_sizes, int n_in,
                              void* d_out, int out_size) {
    const float* x      = (const float*)d_in[0];
    const int*   ei     = (const int*)  d_in[1];
    const float* ea     = (const float*)d_in[2];
    const float* w_edge = (const float*)d_in[3];
    const float* b_edge = (const float*)d_in[4];
    const float* w_root = (const float*)d_in[5];
    const float* b_conv = (const float*)d_in[6];
    const float* W1     = (const float*)d_in[7];
    const float* b1     = (const float*)d_in[8];
    const float* W2     = (const float*)d_in[9];
    const float* b2     = (const float*)d_in[10];
    const float* W3     = (const float*)d_in[11];
    const float* b3     = (const float*)d_in[12];
    float* out = (float*)d_out;

    // zero the accumulator (memset node, graph-capturable, no allocation)
    void* gnodes_ptr = nullptr;
    cudaGetSymbolAddress(&gnodes_ptr, g_nodes);
    cudaMemsetAsync(gnodes_ptr, 0, NTOT * sizeof(float));

    edge_kernel<<<EVEC / ETPB, ETPB>>>(ei, ea, x, w_edge, b_edge);
    head_kernel<<<G_ / GPB, GPB>>>(x, w_root, b_conv,
                                   W1, b1, W2, b2, W3, b3, out);
}

// round 17
// speedup vs baseline: 1.0051x; 1.0051x over previous
#include <cuda_runtime.h>

// Problem constants (fixed by the reference)
#define G_   131072
#define NPG_ 38
#define NTOT (G_ * NPG_)        // 4,980,736 nodes
#define ETOT (10 * NTOT)        // 49,807,360 edges

// Per-node aggregate scratch (~19.9 MB static device array).
// Zeroed by a memset node each replay; edge atomics accumulate into it;
// head kernel adds the root term on read.
__device__ float g_nodes[NTOT];

// ---------------------------------------------------------------------------
// Edge kernel (FINAL, R15 best): per-edge message + scatter-add,
// 4 edges/thread, one-shot launch, TPB=512.
//   theta = edge_attr * w_edge + b_edge
//   g_nodes[dst] += x[src] * theta        (RED.ADD, spread addresses)
// At the joint HW floor: ~2.0 cyc/edge/SM of L1tex wavefront work + LTS
// sector traffic ~85% of the ~6300 B/cyc cap; DRAM carries only the
// irreducible 600MB edge stream (gathers are L2 hits).
// Measured bracket: TPB 256=401.4 / 512=399.7 / 1024=401.4;
// 8 edges/thread neutral (R2); persistent grid-stride +80us (R12);
// __ldcs on streams worth ~8us (R3).
// ---------------------------------------------------------------------------
#define EVEC (ETOT / 4)         // 12,451,840 vec4 edge-groups
#define ETPB 512

__global__ void __launch_bounds__(ETPB)
edge_kernel(const int*   __restrict__ edge_index,
            const float* __restrict__ edge_attr,
            const float* __restrict__ x,
            const float* __restrict__ w_edge,
            const float* __restrict__ b_edge) {
    int i = blockIdx.x * blockDim.x + threadIdx.x;   // over EVEC
    const int4*   src4 = reinterpret_cast<const int4*>(edge_index);
    const int4*   dst4 = reinterpret_cast<const int4*>(edge_index + ETOT);
    const float4* ea4  = reinterpret_cast<const float4*>(edge_attr);

    int4   s = __ldcs(&src4[i]);
    int4   d = __ldcs(&dst4[i]);
    float4 a = __ldcs(&ea4[i]);

    const float we = __ldg(w_edge);
    const float be = __ldg(b_edge);

    // independent gathers first (MLP), then the reductions
    float x0 = __ldg(x + s.x);
    float x1 = __ldg(x + s.y);
    float x2 = __ldg(x + s.z);
    float x3 = __ldg(x + s.w);

    atomicAdd(g_nodes + d.x, x0 * fmaf(a.x, we, be));
    atomicAdd(g_nodes + d.y, x1 * fmaf(a.y, we, be));
    atomicAdd(g_nodes + d.z, x2 * fmaf(a.z, we, be));
    atomicAdd(g_nodes + d.w, x3 * fmaf(a.w, we, be));
}

// ---------------------------------------------------------------------------
// Head kernel (FINAL, R11 best): nodes = g_nodes + x*w_root + b_conv,
// then per-graph MLP 38 -> 4 -> 4 -> 12 + softmax.
// 128 graphs/block (grid=1024), 1 thread per graph.  Staging loop fully
// unrolled (10 predicated iters) so ptxas batches the independent LDG.128s
// ahead of the shared stores; __launch_bounds__(128,7) gives the 72-reg
// budget for that batching without losing resident warps (grid-limited to
// 7 blocks/SM).  READ-ONLY staging (R7: stores into g_nodes cost +40us).
// ---------------------------------------------------------------------------
#define GPB   128
#define NVEC  ((GPB * NPG_) / 4)   // 1216 float4 per block

__global__ void __launch_bounds__(GPB, 7)
head_kernel(const float* __restrict__ x,
            const float* __restrict__ w_root, const float* __restrict__ b_conv,
            const float* __restrict__ W1, const float* __restrict__ b1,
            const float* __restrict__ W2, const float* __restrict__ b2,
            const float* __restrict__ W3, const float* __restrict__ b3,
            float* __restrict__ out) {
    __shared__ float sW1[NPG_ * 4];
    __shared__ float sb1[4];
    __shared__ float sW2[16];
    __shared__ float sb2[4];
    __shared__ float sW3[48];
    __shared__ float sb3[12];
    __shared__ float4 sn4[NVEC];               // linear GPB*38 floats

    const int t = threadIdx.x;

    // weight staging (block has 128 threads)
    if (t < 4)   sb1[t] = b1[t];
    if (t < 16)  sW2[t] = W2[t];
    if (t >= 16 && t < 20)  sb2[t - 16] = b2[t - 16];
    if (t >= 32 && t < 44)  sb3[t - 32] = b3[t - 32];
    if (t >= 48 && t < 96)  sW3[t - 48] = W3[t - 48];
    if (t < NPG_ * 4 - 128) sW1[128 + t] = W1[128 + t];  // elems 128..151
    sW1[t] = W1[t];                                      // elems 0..127

    const float wr = __ldg(w_root);
    const float bc = __ldg(b_conv);

    const long long base = (long long)blockIdx.x * (GPB * NPG_);
    const float4* agg4 = reinterpret_cast<const float4*>(g_nodes + base);
    const float4* x4   = reinterpret_cast<const float4*>(x + base);

    // staging: fold root term. Fully unrolled -> batched independent LDGs.
#pragma unroll
    for (int j = 0; j < 10; j++) {
        int k = t + j * GPB;
        if (k < NVEC) {
            float4 av = __ldcs(&agg4[k]);     // dead after this read
            float4 xv = __ldcs(&x4[k]);       // dead after this read
            float4 v;
            v.x = fmaf(xv.x, wr, bc) + av.x;
            v.y = fmaf(xv.y, wr, bc) + av.y;
            v.z = fmaf(xv.z, wr, bc) + av.z;
            v.w = fmaf(xv.w, wr, bc) + av.w;
            sn4[k] = v;
        }
    }
    __syncthreads();

    const float* h0 = reinterpret_cast<const float*>(sn4) + t * NPG_;

    // layer 1: 38 -> 4
    float h1[4];
#pragma unroll
    for (int j = 0; j < 4; j++) h1[j] = sb1[j];
#pragma unroll
    for (int k = 0; k < NPG_; k++) {
        float v = h0[k];
#pragma unroll
        for (int j = 0; j < 4; j++) h1[j] = fmaf(v, sW1[k * 4 + j], h1[j]);
    }
#pragma unroll
    for (int j = 0; j < 4; j++) h1[j] = (h1[j] >= 0.0f) ? h1[j] : 0.01f * h1[j];

    // layer 2: 4 -> 4
    float h2[4];
#pragma unroll
    for (int j = 0; j < 4; j++) h2[j] = sb2[j];
#pragma unroll
    for (int k = 0; k < 4; k++) {
        float v = h1[k];
#pragma unroll
        for (int j = 0; j < 4; j++) h2[j] = fmaf(v, sW2[k * 4 + j], h2[j]);
    }
#pragma unroll
    for (int j = 0; j < 4; j++) h2[j] = (h2[j] >= 0.0f) ? h2[j] : 0.01f * h2[j];

    // layer 3: 4 -> 12
    float h3[12];
#pragma unroll
    for (int j = 0; j < 12; j++) h3[j] = sb3[j];
#pragma unroll
    for (int k = 0; k < 4; k++) {
        float v = h2[k];
#pragma unroll
        for (int j = 0; j < 12; j++) h3[j] = fmaf(v, sW3[k * 12 + j], h3[j]);
    }
#pragma unroll
    for (int j = 0; j < 12; j++) h3[j] = (h3[j] >= 0.0f) ? h3[j] : 0.01f * h3[j];

    // stable softmax over 12
    float m = h3[0];
#pragma unroll
    for (int j = 1; j < 12; j++) m = fmaxf(m, h3[j]);
    float ssum = 0.0f;
#pragma unroll
    for (int j = 0; j < 12; j++) {
        h3[j] = __expf(h3[j] - m);
        ssum += h3[j];
    }
    float inv = 1.0f / ssum;

    // 12 floats = 3x STG.128, streaming (output is dead to this kernel)
    float4* o4 = reinterpret_cast<float4*>(out + ((long long)blockIdx.x * GPB + t) * 12);
    float4 o;
    o.x = h3[0] * inv;  o.y = h3[1] * inv;  o.z = h3[2] * inv;  o.w = h3[3] * inv;
    __stcs(&o4[0], o);
    o.x = h3[4] * inv;  o.y = h3[5] * inv;  o.z = h3[6] * inv;  o.w = h3[7] * inv;
    __stcs(&o4[1], o);
    o.x = h3[8] * inv;  o.y = h3[9] * inv;  o.z = h3[10] * inv; o.w = h3[11] * inv;
    __stcs(&o4[2], o);
}

// ---------------------------------------------------------------------------
// Launch.  Inputs: x, edge_index, edge_attr, w_edge, b_edge, w_root, b_conv,
//                  W1, b1, W2, b2, W3, b3
// ---------------------------------------------------------------------------
extern "C" void kernel_launch(void* const* d_in, const int* in_sizes, int n_in,
                              void* d_out, int out_size) {
    const float* x      = (const float*)d_in[0];
    const int*   ei     = (const int*)  d_in[1];
    const float* ea     = (const float*)d_in[2];
    const float* w_edge = (const float*)d_in[3];
    const float* b_edge = (const float*)d_in[4];
    const float* w_root = (const float*)d_in[5];
    const float* b_conv = (const float*)d_in[6];
    const float* W1     = (const float*)d_in[7];
    const float* b1     = (const float*)d_in[8];
    const float* W2     = (const float*)d_in[9];
    const float* b2     = (const float*)d_in[10];
    const float* W3     = (const float*)d_in[11];
    const float* b3     = (const float*)d_in[12];
    float* out = (float*)d_out;

    // zero the accumulator (memset node, graph-capturable, no allocation)
    void* gnodes_ptr = nullptr;
    cudaGetSymbolAddress(&gnodes_ptr, g_nodes);
    cudaMemsetAsync(gnodes_ptr, 0, NTOT * sizeof(float));

    edge_kernel<<<EVEC / ETPB, ETPB>>>(ei, ea, x, w_edge, b_edge);
    head_kernel<<<G_ / GPB, GPB>>>(x, w_root, b_conv,
                                   W1, b1, W2, b2, W3, b3, out);
}